// round 15
// baseline (speedup 1.0000x reference)
#include <cuda_runtime.h>

// Problem constants
#define BATCH    32
#define CH       2048
#define SZ       4096

// Fused kernel in R6's EXACT streaming geometry:
//   16 c-groups x 8 s-threads = 128 threads/block  (R6: 128 thr/block)
//   grid (8 batch-groups, 128 s-tiles) = 1024 blocks (R6: 1024 blocks)
//   per thread: BG=4, float4 of s, CCHUNK=128 c-iters, unroll 4 (identical)
// => same 131072 threads, 8 blocks/SM residency, fine-grained balance that
//    sustained 7.25 TB/s in R2/R6 — with only an 8KB smem reduce appended.
#define C_GROUPS   16
#define S_THREADS  8
#define TPB        (C_GROUPS * S_THREADS)     // 128
#define CCHUNK     (CH / C_GROUPS)            // 128 c-iterations per group
#define BG         4                          // batches per block (w L2 reuse)
#define S_PER_BLOCK (S_THREADS * 4)           // 32 s-columns per block

// Streaming load (evict-first): 1 GiB of x must not thrash w out of L2
__device__ __forceinline__ float4 ldcs4(const float* p) {
    float4 v;
    asm volatile("ld.global.cs.v4.f32 {%0,%1,%2,%3}, [%4];"
                 : "=f"(v.x), "=f"(v.y), "=f"(v.z), "=f"(v.w) : "l"(p));
    return v;
}

__global__ __launch_bounds__(TPB) void CWG_fused_kernel(
    const float* __restrict__ x,
    const float* __restrict__ w,
    const float* __restrict__ bias,
    float* __restrict__ out)
{
    const int s_t = threadIdx.x & (S_THREADS - 1);   // 0..7
    const int cg  = threadIdx.x >> 3;                // 0..15 (c-split)
    const int s0  = blockIdx.y * S_PER_BLOCK + s_t * 4;
    const int b0  = blockIdx.x * BG;                 // batch fastest-varying:
    const int c0  = cg * CCHUNK;                     // same-w blocks co-scheduled

    float4 acc[BG];
#pragma unroll
    for (int b = 0; b < BG; b++) acc[b] = make_float4(0.f, 0.f, 0.f, 0.f);

    const float* wp = w + (size_t)c0 * SZ + s0;
    const float* xp = x + ((size_t)b0 * CH + (size_t)c0) * SZ + s0;

    // ---- byte-identical per-thread loop to the R6 streaming kernel ----
#pragma unroll 4
    for (int c = 0; c < CCHUNK; c++) {
        const float4 wv = __ldg((const float4*)(wp + (size_t)c * SZ));
#pragma unroll
        for (int b = 0; b < BG; b++) {
            const float4 xv = ldcs4(xp + ((size_t)b * CH + (size_t)c) * SZ);
            acc[b].x = fmaf(xv.x, wv.x, acc[b].x);
            acc[b].y = fmaf(xv.y, wv.y, acc[b].y);
            acc[b].z = fmaf(xv.z, wv.z, acc[b].z);
            acc[b].w = fmaf(xv.w, wv.w, acc[b].w);
        }
    }

    // ---- 16-way c-group reduction via shared memory (8 KB) ----
    __shared__ float4 smem[C_GROUPS][S_THREADS][BG];
#pragma unroll
    for (int b = 0; b < BG; b++)
        smem[cg][s_t][b] = acc[b];
    __syncthreads();

    // 32 worker threads: one (s-position, batch) float4 output each.
    const int wk = threadIdx.x;
    if (wk < S_THREADS * BG) {
        const int b  = wk >> 3;                    // 0..3
        const int st = wk & (S_THREADS - 1);       // 0..7
        float4 sum = make_float4(0.f, 0.f, 0.f, 0.f);
#pragma unroll
        for (int g = 0; g < C_GROUPS; g++) {       // ascending g == R6's k-order
            const float4 p = smem[g][st][b];
            sum.x += p.x; sum.y += p.y; sum.z += p.z; sum.w += p.w;
        }
        const int sc = blockIdx.y * S_PER_BLOCK + st * 4;
        const float4 bv = *(const float4*)(bias + sc);
        float4 r;
        r.x = fmaxf(sum.x + bv.x, 0.f);
        r.y = fmaxf(sum.y + bv.y, 0.f);
        r.z = fmaxf(sum.z + bv.z, 0.f);
        r.w = fmaxf(sum.w + bv.w, 0.f);
        *(float4*)(out + (size_t)(b0 + b) * SZ + sc) = r;
    }
}

extern "C" void kernel_launch(void* const* d_in, const int* in_sizes, int n_in,
                              void* d_out, int out_size)
{
    const float* x    = (const float*)d_in[0];
    const float* w    = (const float*)d_in[1];
    const float* bias = (const float*)d_in[2];
    float* out        = (float*)d_out;

    // 8 batch-groups (fastest) x 128 s-tiles = 1024 blocks (R6 geometry).
    dim3 grid(BATCH / BG, SZ / S_PER_BLOCK);
    CWG_fused_kernel<<<grid, TPB>>>(x, w, bias, out);
}

// round 17
// speedup vs baseline: 1.4347x; 1.4347x over previous
#include <cuda_runtime.h>
#include <cstdint>

// Problem constants
#define BATCH    32
#define CH       2048
#define SZ       4096

// R14 geometry (best: 156.1us): 16 c-groups x 16 s-threads = 256 thr/block,
// grid (8 batch-groups, 64 s-tiles) = 512 blocks = 131072 threads.
// Single change: w loads carry an L2::evict_last cache-hint policy (legal
// encoding for sm_103: createpolicy + ld.global.nc.L2::cache_hint.v4.f32),
// pinning the 32MB weight matrix in L2 across batch-groups and graph replays.
#define C_GROUPS   16
#define S_THREADS  16
#define TPB        (C_GROUPS * S_THREADS)     // 256
#define CCHUNK     (CH / C_GROUPS)            // 128 c-iterations per group
#define BG         4                          // batches per block
#define S_PER_BLOCK (S_THREADS * 4)           // 64 s-columns per block

// Streaming load (evict-first): 1 GiB of x must not thrash w out of L2
__device__ __forceinline__ float4 ldcs4(const float* p) {
    float4 v;
    asm volatile("ld.global.cs.v4.f32 {%0,%1,%2,%3}, [%4];"
                 : "=f"(v.x), "=f"(v.y), "=f"(v.z), "=f"(v.w) : "l"(p));
    return v;
}

// Weight load: non-coherent + L2 evict_last via cache-hint policy.
__device__ __forceinline__ float4 ldwl4(const float* p, uint64_t pol) {
    float4 v;
    asm volatile("ld.global.nc.L2::cache_hint.v4.f32 {%0,%1,%2,%3}, [%4], %5;"
                 : "=f"(v.x), "=f"(v.y), "=f"(v.z), "=f"(v.w)
                 : "l"(p), "l"(pol));
    return v;
}

__global__ __launch_bounds__(TPB) void CWG_fused_kernel(
    const float* __restrict__ x,
    const float* __restrict__ w,
    const float* __restrict__ bias,
    float* __restrict__ out)
{
    const int s_t = threadIdx.x & (S_THREADS - 1);   // 0..15
    const int cg  = threadIdx.x >> 4;                // 0..15 (c-split)
    const int s0  = blockIdx.y * S_PER_BLOCK + s_t * 4;
    const int b0  = blockIdx.x * BG;                 // batch fastest-varying:
    const int c0  = cg * CCHUNK;                     // same-w blocks co-scheduled

    // evict_last policy for all weight loads (hoisted, one createpolicy)
    uint64_t wpol;
    asm volatile("createpolicy.fractional.L2::evict_last.b64 %0, 1.0;" : "=l"(wpol));

    float4 acc[BG];
#pragma unroll
    for (int b = 0; b < BG; b++) acc[b] = make_float4(0.f, 0.f, 0.f, 0.f);

    const float* wp = w + (size_t)c0 * SZ + s0;
    const float* xp = x + ((size_t)b0 * CH + (size_t)c0) * SZ + s0;

#pragma unroll 4
    for (int c = 0; c < CCHUNK; c++) {
        const float4 wv = ldwl4(wp + (size_t)c * SZ, wpol);
#pragma unroll
        for (int b = 0; b < BG; b++) {
            const float4 xv = ldcs4(xp + ((size_t)b * CH + (size_t)c) * SZ);
            acc[b].x = fmaf(xv.x, wv.x, acc[b].x);
            acc[b].y = fmaf(xv.y, wv.y, acc[b].y);
            acc[b].z = fmaf(xv.z, wv.z, acc[b].z);
            acc[b].w = fmaf(xv.w, wv.w, acc[b].w);
        }
    }

    // ---- 16-way c-group reduction via shared memory (16 KB) ----
    __shared__ float4 smem[C_GROUPS][S_THREADS][BG];
#pragma unroll
    for (int b = 0; b < BG; b++)
        smem[cg][s_t][b] = acc[b];
    __syncthreads();

    // 64 worker threads: one (s-position, batch) float4 output each.
    const int wk = threadIdx.x;
    if (wk < S_THREADS * BG) {
        const int b  = wk >> 4;                    // 0..3
        const int st = wk & (S_THREADS - 1);       // 0..15
        float4 sum = make_float4(0.f, 0.f, 0.f, 0.f);
#pragma unroll
        for (int g = 0; g < C_GROUPS; g++) {       // ascending g == fixed order
            const float4 p = smem[g][st][b];
            sum.x += p.x; sum.y += p.y; sum.z += p.z; sum.w += p.w;
        }
        const int sc = blockIdx.y * S_PER_BLOCK + st * 4;
        const float4 bv = *(const float4*)(bias + sc);
        float4 r;
        r.x = fmaxf(sum.x + bv.x, 0.f);
        r.y = fmaxf(sum.y + bv.y, 0.f);
        r.z = fmaxf(sum.z + bv.z, 0.f);
        r.w = fmaxf(sum.w + bv.w, 0.f);
        *(float4*)(out + (size_t)(b0 + b) * SZ + sc) = r;
    }
}

extern "C" void kernel_launch(void* const* d_in, const int* in_sizes, int n_in,
                              void* d_out, int out_size)
{
    const float* x    = (const float*)d_in[0];
    const float* w    = (const float*)d_in[1];
    const float* bias = (const float*)d_in[2];
    float* out        = (float*)d_out;

    // 8 batch-groups (fastest) x 64 s-tiles = 512 blocks, 4/SM co-resident.
    dim3 grid(BATCH / BG, SZ / S_PER_BLOCK);
    CWG_fused_kernel<<<grid, TPB>>>(x, w, bias, out);
}